// round 7
// baseline (speedup 1.0000x reference)
#include <cuda_runtime.h>
#include <cuda_bf16.h>
#include <cstdint>

// Problem dims
#define DD 1024
#define MM 512
#define CC 256
#define BB 8192
#define NS_ITERS 12

// ---------------- scratch (device globals; no allocation allowed) ----------
__device__ __align__(16) float g_state_p[DD * BB];   // 32 MB
__device__ __align__(16) float g_FS[DD * DD];
__device__ __align__(16) float g_cov_p[DD * DD];
__device__ __align__(16) float g_innov[MM * BB];     // 16 MB
__device__ __align__(16) float g_HP[MM * DD];
__device__ __align__(16) float g_S[MM * MM];
__device__ __align__(16) float g_X[MM * MM];
__device__ __align__(16) float g_X2[MM * MM];
__device__ __align__(16) float g_T[MM * MM];
__device__ __align__(16) float g_PHt[DD * MM];
__device__ __align__(16) float g_K[DD * MM];
__device__ __align__(16) float g_Ft[DD * DD];        // F^T
__device__ __align__(16) float g_Ht[DD * MM];        // H^T
__device__ __align__(16) float g_norms[2];

// ---------------- fp32 transpose: out[c][r] = in[r][c] ----------------------
__global__ void transpose_kernel(const float* __restrict__ in,
                                 float* __restrict__ out, int R, int C)
{
    __shared__ float t[32][33];
    const int r0 = blockIdx.y * 32, c0 = blockIdx.x * 32;
    const int tx = threadIdx.x, ty = threadIdx.y;  // 32 x 8
#pragma unroll
    for (int i = 0; i < 32; i += 8)
        t[ty + i][tx] = in[(size_t)(r0 + ty + i) * C + c0 + tx];
    __syncthreads();
#pragma unroll
    for (int i = 0; i < 32; i += 8)
        out[(size_t)(c0 + ty + i) * R + r0 + tx] = t[tx][ty + i];
}

// ======================= fused split-2 bf16 tensor-core GEMM ================
// C = alpha * A@B + beta * Cin, computed as Ah.Bh + Ah.Bl + Al.Bh where
// x = bf16_hi(x) + bf16_lo(x - hi). A [M,K], B [K,N] fp32 row-major; the
// hi/lo conversion happens in registers during smem staging (no split pass).
// Block 128x128, BK=16, 8 warps of 32x64, mma.sync m16n8k16. Fragments via
// plain shared loads per the documented m16n8k16 layout (g=lane>>2, t=lane&3).
__device__ __forceinline__ void mma16816(float c[4], const uint32_t a[4],
                                         uint32_t b0, uint32_t b1) {
    asm volatile("mma.sync.aligned.m16n8k16.row.col.f32.bf16.bf16.f32 "
                 "{%0,%1,%2,%3}, {%4,%5,%6,%7}, {%8,%9}, {%0,%1,%2,%3};"
                 : "+f"(c[0]), "+f"(c[1]), "+f"(c[2]), "+f"(c[3])
                 : "r"(a[0]), "r"(a[1]), "r"(a[2]), "r"(a[3]), "r"(b0), "r"(b1));
}

__device__ __forceinline__ void cvt8_store(const float4& v0, const float4& v1,
                                           __nv_bfloat16* hi, __nv_bfloat16* lo)
{
    union { uint4 u; __nv_bfloat16 h[8]; } H, L;
    const float f[8] = {v0.x, v0.y, v0.z, v0.w, v1.x, v1.y, v1.z, v1.w};
#pragma unroll
    for (int i = 0; i < 8; i++) {
        H.h[i] = __float2bfloat16_rn(f[i]);
        L.h[i] = __float2bfloat16_rn(f[i] - __bfloat162float(H.h[i]));
    }
    *(uint4*)hi = H.u;
    *(uint4*)lo = L.u;
}

__global__ __launch_bounds__(256)
void tcgemm(int M, int N, int K,
            const float* __restrict__ A, const float* __restrict__ B,
            const float* __restrict__ Cin, float* __restrict__ Cout,
            float alpha, float beta)
{
    constexpr int SA = 24;    // A smem row stride (elems): conflict-free frags
    constexpr int SBN = 136;  // B smem row stride (elems): conflict-free frags
    __shared__ alignas(16) __nv_bfloat16 sAh[128 * SA];
    __shared__ alignas(16) __nv_bfloat16 sAl[128 * SA];
    __shared__ alignas(16) __nv_bfloat16 sBh[16 * SBN];
    __shared__ alignas(16) __nv_bfloat16 sBl[16 * SBN];

    const int tid = threadIdx.x;
    const int wid = tid / 32, lane = tid % 32;
    const int warpM = wid / 2, warpN = wid % 2;
    const int g = lane >> 2, t = lane & 3;
    const int bm = blockIdx.y * 128, bn = blockIdx.x * 128;

    // global->smem mapping: 8 fp32 elems (2 float4) per thread per array
    const int arow = tid >> 1, acol = (tid & 1) * 8;    // 128 rows x 16
    const int brow = tid >> 4, bcol = (tid & 15) * 8;   // 16 rows x 128

    float4 a0, a1, b0, b1;
    auto ldg = [&](int k0) {
        const float* ap = A + (size_t)(bm + arow) * K + k0 + acol;
        a0 = *(const float4*)(ap);
        a1 = *(const float4*)(ap + 4);
        const float* bp = B + (size_t)(k0 + brow) * N + bn + bcol;
        b0 = *(const float4*)(bp);
        b1 = *(const float4*)(bp + 4);
    };
    auto sts = [&]() {
        cvt8_store(a0, a1, &sAh[arow * SA + acol], &sAl[arow * SA + acol]);
        cvt8_store(b0, b1, &sBh[brow * SBN + bcol], &sBl[brow * SBN + bcol]);
    };

    float acc[2][8][4];
#pragma unroll
    for (int mt = 0; mt < 2; mt++)
#pragma unroll
        for (int nt = 0; nt < 8; nt++)
#pragma unroll
            for (int q = 0; q < 4; q++) acc[mt][nt][q] = 0.f;

    const unsigned short* uBh = (const unsigned short*)sBh;
    const unsigned short* uBl = (const unsigned short*)sBl;

    ldg(0);
    for (int k0 = 0; k0 < K; k0 += 16) {
        sts();
        __syncthreads();
        if (k0 + 16 < K) ldg(k0 + 16);

        uint32_t ah[2][4], al[2][4];
#pragma unroll
        for (int mt = 0; mt < 2; mt++) {
            const int r = warpM * 32 + mt * 16;
            ah[mt][0] = *(const uint32_t*)&sAh[(r + g) * SA + 2 * t];
            ah[mt][1] = *(const uint32_t*)&sAh[(r + g + 8) * SA + 2 * t];
            ah[mt][2] = *(const uint32_t*)&sAh[(r + g) * SA + 2 * t + 8];
            ah[mt][3] = *(const uint32_t*)&sAh[(r + g + 8) * SA + 2 * t + 8];
            al[mt][0] = *(const uint32_t*)&sAl[(r + g) * SA + 2 * t];
            al[mt][1] = *(const uint32_t*)&sAl[(r + g + 8) * SA + 2 * t];
            al[mt][2] = *(const uint32_t*)&sAl[(r + g) * SA + 2 * t + 8];
            al[mt][3] = *(const uint32_t*)&sAl[(r + g + 8) * SA + 2 * t + 8];
        }
#pragma unroll
        for (int ng = 0; ng < 8; ng++) {
            const int n = warpN * 64 + ng * 8 + g;
            uint32_t bh0 = (uint32_t)uBh[(2 * t) * SBN + n]
                         | ((uint32_t)uBh[(2 * t + 1) * SBN + n] << 16);
            uint32_t bh1 = (uint32_t)uBh[(2 * t + 8) * SBN + n]
                         | ((uint32_t)uBh[(2 * t + 9) * SBN + n] << 16);
            uint32_t bl0 = (uint32_t)uBl[(2 * t) * SBN + n]
                         | ((uint32_t)uBl[(2 * t + 1) * SBN + n] << 16);
            uint32_t bl1 = (uint32_t)uBl[(2 * t + 8) * SBN + n]
                         | ((uint32_t)uBl[(2 * t + 9) * SBN + n] << 16);
#pragma unroll
            for (int mt = 0; mt < 2; mt++) {
                mma16816(acc[mt][ng], ah[mt], bh0, bh1);
                mma16816(acc[mt][ng], ah[mt], bl0, bl1);
                mma16816(acc[mt][ng], al[mt], bh0, bh1);
            }
        }
        __syncthreads();
    }

    // epilogue: c0,c1 at (row g, cols 2t,2t+1); c2,c3 at (row g+8, same)
#pragma unroll
    for (int mt = 0; mt < 2; mt++) {
        const int rowb = bm + warpM * 32 + mt * 16;
#pragma unroll
        for (int nt = 0; nt < 8; nt++) {
            const int col = bn + warpN * 64 + nt * 8 + 2 * t;
            const int r0 = rowb + g, r1 = rowb + g + 8;
            float2 c01 = make_float2(alpha * acc[mt][nt][0], alpha * acc[mt][nt][1]);
            float2 c23 = make_float2(alpha * acc[mt][nt][2], alpha * acc[mt][nt][3]);
            if (beta != 0.f) {
                float2 p0 = *(const float2*)(Cin + (size_t)r0 * N + col);
                float2 p1 = *(const float2*)(Cin + (size_t)r1 * N + col);
                c01.x += beta * p0.x; c01.y += beta * p0.y;
                c23.x += beta * p1.x; c23.y += beta * p1.y;
            }
            *(float2*)(Cout + (size_t)r0 * N + col) = c01;
            *(float2*)(Cout + (size_t)r1 * N + col) = c23;
        }
    }
}

// ---------------- Newton-Schulz support ------------------------------------
__global__ void zero_norms_kernel(float* norms) {
    if (threadIdx.x < 2) norms[threadIdx.x] = 0.f;
}
__global__ void snorms_kernel(const float* __restrict__ S, float* norms) {
    __shared__ float sr[256], sc[256];
    const int i = blockIdx.x;
    float r = 0.f, c = 0.f;
    for (int j = threadIdx.x; j < MM; j += 256) {
        r += fabsf(S[(size_t)i * MM + j]);
        c += fabsf(S[(size_t)j * MM + i]);
    }
    sr[threadIdx.x] = r; sc[threadIdx.x] = c;
    __syncthreads();
    for (int o = 128; o > 0; o >>= 1) {
        if (threadIdx.x < o) {
            sr[threadIdx.x] += sr[threadIdx.x + o];
            sc[threadIdx.x] += sc[threadIdx.x + o];
        }
        __syncthreads();
    }
    if (threadIdx.x == 0) {
        atomicMax((int*)&norms[0], __float_as_int(sr[0]));
        atomicMax((int*)&norms[1], __float_as_int(sc[0]));
    }
}
// X0 = S^T / (||S||_inf * ||S||_1)
__global__ void init_X_kernel(const float* __restrict__ S,
                              const float* __restrict__ norms,
                              float* __restrict__ X) {
    const float scale = 1.f / (norms[0] * norms[1]);
    const int idx = blockIdx.x * blockDim.x + threadIdx.x;
    const int i = idx / MM, j = idx % MM;
    X[idx] = S[(size_t)j * MM + i] * scale;
}

// ---------------- host-side dispatch ----------------------------------------
static void tc(int M, int N, int K, const float* A, const float* B,
               const float* Cin, float* C, float alpha, float beta)
{
    dim3 grd(N / 128, M / 128);
    tcgemm<<<grd, 256>>>(M, N, K, A, B, Cin, C, alpha, beta);
}

extern "C" void kernel_launch(void* const* d_in, const int* in_sizes, int n_in,
                              void* d_out, int out_size)
{
    (void)in_sizes; (void)n_in; (void)out_size;
    const float* state     = (const float*)d_in[0];
    const float* state_cov = (const float*)d_in[1];
    const float* meas      = (const float*)d_in[2];
    const float* control   = (const float*)d_in[3];
    const float* F         = (const float*)d_in[4];
    const float* Q         = (const float*)d_in[5];
    const float* Bc        = (const float*)d_in[6];
    const float* H         = (const float*)d_in[7];
    const float* R         = (const float*)d_in[8];
    float* out_state = (float*)d_out;
    float* out_cov   = out_state + (size_t)DD * BB;

    float *sp, *fs, *cp, *innov, *hp, *S, *X, *X2, *T, *pht, *Kg, *Ft, *Ht, *norms;
    cudaGetSymbolAddress((void**)&sp,    g_state_p);
    cudaGetSymbolAddress((void**)&fs,    g_FS);
    cudaGetSymbolAddress((void**)&cp,    g_cov_p);
    cudaGetSymbolAddress((void**)&innov, g_innov);
    cudaGetSymbolAddress((void**)&hp,    g_HP);
    cudaGetSymbolAddress((void**)&S,     g_S);
    cudaGetSymbolAddress((void**)&X,     g_X);
    cudaGetSymbolAddress((void**)&X2,    g_X2);
    cudaGetSymbolAddress((void**)&T,     g_T);
    cudaGetSymbolAddress((void**)&pht,   g_PHt);
    cudaGetSymbolAddress((void**)&Kg,    g_K);
    cudaGetSymbolAddress((void**)&Ft,    g_Ft);
    cudaGetSymbolAddress((void**)&Ht,    g_Ht);
    cudaGetSymbolAddress((void**)&norms, g_norms);

    // ---- transposes (tiny) ----
    transpose_kernel<<<dim3(DD / 32, DD / 32), dim3(32, 8)>>>(F, Ft, DD, DD);
    transpose_kernel<<<dim3(DD / 32, MM / 32), dim3(32, 8)>>>(H, Ht, MM, DD);

    // ---- prediction ----
    tc(DD, BB, DD, F, state, nullptr, sp, 1.f, 0.f);        // sp = F @ state
    tc(DD, DD, DD, F, state_cov, nullptr, fs, 1.f, 0.f);    // fs = F @ Sigma
    tc(DD, DD, DD, fs, Ft, Q, cp, 1.f, 1.f);                // cp = fs @ F^T + Q
    tc(DD, BB, CC, Bc, control, sp, sp, 1.f, 1.f);          // sp += Bc @ control

    // ---- correction ----
    tc(MM, BB, DD, H, sp, meas, innov, -1.f, 1.f);          // innov = meas - H@sp
    tc(MM, DD, DD, H, cp, nullptr, hp, 1.f, 0.f);           // hp = H @ cp
    tc(MM, MM, DD, hp, Ht, R, S, 1.f, 1.f);                 // S = hp @ H^T + R
    tc(DD, MM, DD, cp, Ht, nullptr, pht, 1.f, 0.f);         // pht = cp @ H^T

    // ---- Newton-Schulz inverse of S (tensor cores) ----
    zero_norms_kernel<<<1, 32>>>(norms);
    snorms_kernel<<<MM, 256>>>(S, norms);
    init_X_kernel<<<(MM * MM) / 256, 256>>>(S, norms, X);
    float* cur = X;
    float* nxt = X2;
    for (int it = 0; it < NS_ITERS; ++it) {
        tc(MM, MM, MM, S,   cur, nullptr, T,   1.f, 0.f);   // T = S @ X
        tc(MM, MM, MM, cur, T,   cur,     nxt, -1.f, 2.f);  // X' = 2X - X@T
        float* tmpp = cur; cur = nxt; nxt = tmpp;
    }
    // cur == S^{-1}

    // ---- gain + outputs ----
    tc(DD, MM, MM, pht, cur, nullptr, Kg, 1.f, 0.f);        // K = pht @ S^{-1}
    tc(DD, BB, MM, Kg, innov, sp, out_state, 1.f, 1.f);     // state_n
    tc(DD, DD, MM, Kg, hp, cp, out_cov, -1.f, 1.f);         // cov_n = cp - K@hp
}

// round 8
// speedup vs baseline: 1.3656x; 1.3656x over previous
#include <cuda_runtime.h>
#include <cuda_bf16.h>
#include <cstdint>

#define DD 1024
#define MM 512
#define CC 256
#define BB 8192
#define NS_ITERS 12

typedef __nv_bfloat16 bf16;

// ---------------- scratch (device globals; no allocation allowed) ----------
__device__ __align__(16) float g_state_p[DD * BB];   // 32 MB
__device__ __align__(16) float g_FS[DD * DD];
__device__ __align__(16) float g_cov_p[DD * DD];
__device__ __align__(16) float g_innov[MM * BB];     // 16 MB
__device__ __align__(16) float g_HP[MM * DD];
__device__ __align__(16) float g_S[MM * MM];
__device__ __align__(16) float g_X[MM * MM];
__device__ __align__(16) float g_X2[MM * MM];
__device__ __align__(16) float g_T[MM * MM];
__device__ __align__(16) float g_PHt[DD * MM];
__device__ __align__(16) float g_K[DD * MM];
// planes: A [M,K] row-major; B [N,K] (i.e. B^T) row-major
__device__ __align__(16) bf16 g_Ah[DD * DD], g_Al[DD * DD];      // 2 MB each
__device__ __align__(16) bf16 g_Bh[DD * BB], g_Bl[DD * BB];      // 16 MB each
__device__ __align__(16) bf16 g_SAh[MM * MM], g_SAl[MM * MM];    // S planes (NS)
__device__ __align__(16) float g_norms[2];

// ---------------- split helpers --------------------------------------------
__device__ __forceinline__ void hl(float v, bf16& h, bf16& l) {
    h = __float2bfloat16_rn(v);
    l = __float2bfloat16_rn(v - __bfloat162float(h));
}

// plain split: planes same layout as src [R,C]
__global__ void split_kernel(const float4* __restrict__ in,
                             bf16* __restrict__ hi, bf16* __restrict__ lo, int n4)
{
    int i = blockIdx.x * blockDim.x + threadIdx.x;
    if (i >= n4) return;
    float4 v = in[i];
    bf16 h0, h1, h2, h3, l0, l1, l2, l3;
    hl(v.x, h0, l0); hl(v.y, h1, l1); hl(v.z, h2, l2); hl(v.w, h3, l3);
    ((__nv_bfloat162*)hi)[2 * i + 0] = __nv_bfloat162(h0, h1);
    ((__nv_bfloat162*)hi)[2 * i + 1] = __nv_bfloat162(h2, h3);
    ((__nv_bfloat162*)lo)[2 * i + 0] = __nv_bfloat162(l0, l1);
    ((__nv_bfloat162*)lo)[2 * i + 1] = __nv_bfloat162(l2, l3);
}

// transpose-split: src [R,C] -> planes [C,R]
__global__ void splitT_kernel(const float* __restrict__ in,
                              bf16* __restrict__ hi, bf16* __restrict__ lo,
                              int R, int C)
{
    __shared__ float t[32][33];
    const int r0 = blockIdx.y * 32, c0 = blockIdx.x * 32;
    const int tx = threadIdx.x, ty = threadIdx.y;  // 32 x 8
#pragma unroll
    for (int i = 0; i < 32; i += 8)
        t[ty + i][tx] = in[(size_t)(r0 + ty + i) * C + c0 + tx];
    __syncthreads();
#pragma unroll
    for (int i = 0; i < 32; i += 8) {
        bf16 h, l; hl(t[tx][ty + i], h, l);
        size_t o = (size_t)(c0 + ty + i) * R + r0 + tx;
        hi[o] = h; lo[o] = l;
    }
}

// both: src [R,C] -> A planes [R,C] AND B planes [C,R]
__global__ void split_both_kernel(const float* __restrict__ in,
                                  bf16* __restrict__ ah, bf16* __restrict__ al,
                                  bf16* __restrict__ bh, bf16* __restrict__ bl,
                                  int R, int C)
{
    __shared__ float t[32][33];
    const int r0 = blockIdx.y * 32, c0 = blockIdx.x * 32;
    const int tx = threadIdx.x, ty = threadIdx.y;
#pragma unroll
    for (int i = 0; i < 32; i += 8) {
        float v = in[(size_t)(r0 + ty + i) * C + c0 + tx];
        t[ty + i][tx] = v;
        bf16 h, l; hl(v, h, l);
        size_t o = (size_t)(r0 + ty + i) * C + c0 + tx;
        ah[o] = h; al[o] = l;
    }
    __syncthreads();
#pragma unroll
    for (int i = 0; i < 32; i += 8) {
        bf16 h, l; hl(t[tx][ty + i], h, l);
        size_t o = (size_t)(c0 + ty + i) * R + r0 + tx;
        bh[o] = h; bl[o] = l;
    }
}

// ======================= plane tensor-core GEMM =============================
// C = alpha * A@B + beta*Cin via split-2 bf16 (lo*lo dropped).
// A planes [M,K]; B planes [N,K] (= B^T). Tile BM x BM, BK=16, 2*BM threads.
// Warps: warpM=wid/2 (32 rows each), warpN=wid%2 (BM/2 cols each).
__device__ __forceinline__ void mma16816(float c[4], const uint32_t a[4],
                                         uint32_t b0, uint32_t b1) {
    asm volatile("mma.sync.aligned.m16n8k16.row.col.f32.bf16.bf16.f32 "
                 "{%0,%1,%2,%3}, {%4,%5,%6,%7}, {%8,%9}, {%0,%1,%2,%3};"
                 : "+f"(c[0]), "+f"(c[1]), "+f"(c[2]), "+f"(c[3])
                 : "r"(a[0]), "r"(a[1]), "r"(a[2]), "r"(a[3]), "r"(b0), "r"(b1));
}

template <int BM>
__global__ __launch_bounds__(2 * BM)
void pgemm(int M, int N, int K,
           const bf16* __restrict__ Ah, const bf16* __restrict__ Al,
           const bf16* __restrict__ Bh, const bf16* __restrict__ Bl,
           const float* __restrict__ Cin, float* __restrict__ Cout,
           float alpha, float beta)
{
    constexpr int SA = 24;        // smem row stride (elems): conflict-free frags
    constexpr int NG = BM / 16;   // 8-col groups per warp
    __shared__ alignas(16) bf16 sAh[BM * SA], sAl[BM * SA];
    __shared__ alignas(16) bf16 sBh[BM * SA], sBl[BM * SA];

    const int tid = threadIdx.x;
    const int wid = tid / 32, lane = tid % 32;
    const int warpM = wid / 2, warpN = wid % 2;
    const int g = lane >> 2, t = lane & 3;
    const int bm = blockIdx.y * BM, bn = blockIdx.x * BM;

    // loader: 1 uint4 (8 bf16) per thread per plane; rows tid>>1, col halves
    const int arow = tid >> 1, acol = (tid & 1) * 8;

    uint4 rah, ral, rbh, rbl;
    auto ldg = [&](int k0) {
        rah = *(const uint4*)(Ah + (size_t)(bm + arow) * K + k0 + acol);
        ral = *(const uint4*)(Al + (size_t)(bm + arow) * K + k0 + acol);
        rbh = *(const uint4*)(Bh + (size_t)(bn + arow) * K + k0 + acol);
        rbl = *(const uint4*)(Bl + (size_t)(bn + arow) * K + k0 + acol);
    };
    auto sts = [&]() {
        *(uint4*)(&sAh[arow * SA + acol]) = rah;
        *(uint4*)(&sAl[arow * SA + acol]) = ral;
        *(uint4*)(&sBh[arow * SA + acol]) = rbh;
        *(uint4*)(&sBl[arow * SA + acol]) = rbl;
    };

    float acc[2][NG][4];
#pragma unroll
    for (int mt = 0; mt < 2; mt++)
#pragma unroll
        for (int nt = 0; nt < NG; nt++)
#pragma unroll
            for (int q = 0; q < 4; q++) acc[mt][nt][q] = 0.f;

    ldg(0);
    for (int k0 = 0; k0 < K; k0 += 16) {
        sts();
        __syncthreads();
        if (k0 + 16 < K) ldg(k0 + 16);

        uint32_t ah[2][4], al[2][4];
#pragma unroll
        for (int mt = 0; mt < 2; mt++) {
            const int r = warpM * 32 + mt * 16;
            ah[mt][0] = *(const uint32_t*)&sAh[(r + g) * SA + 2 * t];
            ah[mt][1] = *(const uint32_t*)&sAh[(r + g + 8) * SA + 2 * t];
            ah[mt][2] = *(const uint32_t*)&sAh[(r + g) * SA + 2 * t + 8];
            ah[mt][3] = *(const uint32_t*)&sAh[(r + g + 8) * SA + 2 * t + 8];
            al[mt][0] = *(const uint32_t*)&sAl[(r + g) * SA + 2 * t];
            al[mt][1] = *(const uint32_t*)&sAl[(r + g + 8) * SA + 2 * t];
            al[mt][2] = *(const uint32_t*)&sAl[(r + g) * SA + 2 * t + 8];
            al[mt][3] = *(const uint32_t*)&sAl[(r + g + 8) * SA + 2 * t + 8];
        }
#pragma unroll
        for (int ng = 0; ng < NG; ng++) {
            const int n = warpN * (BM / 2) + ng * 8 + g;  // plane row (N index)
            uint32_t bh0 = *(const uint32_t*)&sBh[n * SA + 2 * t];
            uint32_t bh1 = *(const uint32_t*)&sBh[n * SA + 2 * t + 8];
            uint32_t bl0 = *(const uint32_t*)&sBl[n * SA + 2 * t];
            uint32_t bl1 = *(const uint32_t*)&sBl[n * SA + 2 * t + 8];
#pragma unroll
            for (int mt = 0; mt < 2; mt++) {
                mma16816(acc[mt][ng], ah[mt], bh0, bh1);
                mma16816(acc[mt][ng], ah[mt], bl0, bl1);
                mma16816(acc[mt][ng], al[mt], bh0, bh1);
            }
        }
        __syncthreads();
    }

    // epilogue: c0,c1 at (row g, cols 2t,2t+1); c2,c3 at (row g+8)
#pragma unroll
    for (int mt = 0; mt < 2; mt++) {
        const int rowb = bm + warpM * 32 + mt * 16;
#pragma unroll
        for (int nt = 0; nt < NG; nt++) {
            const int col = bn + warpN * (BM / 2) + nt * 8 + 2 * t;
            const int r0 = rowb + g, r1 = rowb + g + 8;
            float2 c01 = make_float2(alpha * acc[mt][nt][0], alpha * acc[mt][nt][1]);
            float2 c23 = make_float2(alpha * acc[mt][nt][2], alpha * acc[mt][nt][3]);
            if (beta != 0.f) {
                float2 p0 = *(const float2*)(Cin + (size_t)r0 * N + col);
                float2 p1 = *(const float2*)(Cin + (size_t)r1 * N + col);
                c01.x += beta * p0.x; c01.y += beta * p0.y;
                c23.x += beta * p1.x; c23.y += beta * p1.y;
            }
            *(float2*)(Cout + (size_t)r0 * N + col) = c01;
            *(float2*)(Cout + (size_t)r1 * N + col) = c23;
        }
    }
}

// ---------------- Newton-Schulz support ------------------------------------
__global__ void zero_norms_kernel(float* norms) {
    if (threadIdx.x < 2) norms[threadIdx.x] = 0.f;
}
__global__ void snorms_kernel(const float* __restrict__ S, float* norms) {
    __shared__ float sr[256], sc[256];
    const int i = blockIdx.x;
    float r = 0.f, c = 0.f;
    for (int j = threadIdx.x; j < MM; j += 256) {
        r += fabsf(S[(size_t)i * MM + j]);
        c += fabsf(S[(size_t)j * MM + i]);
    }
    sr[threadIdx.x] = r; sc[threadIdx.x] = c;
    __syncthreads();
    for (int o = 128; o > 0; o >>= 1) {
        if (threadIdx.x < o) {
            sr[threadIdx.x] += sr[threadIdx.x + o];
            sc[threadIdx.x] += sc[threadIdx.x + o];
        }
        __syncthreads();
    }
    if (threadIdx.x == 0) {
        atomicMax((int*)&norms[0], __float_as_int(sr[0]));
        atomicMax((int*)&norms[1], __float_as_int(sc[0]));
    }
}
__global__ void init_X_kernel(const float* __restrict__ S,
                              const float* __restrict__ norms,
                              float* __restrict__ X) {
    const float scale = 1.f / (norms[0] * norms[1]);
    const int idx = blockIdx.x * blockDim.x + threadIdx.x;
    const int i = idx / MM, j = idx % MM;
    X[idx] = S[(size_t)j * MM + i] * scale;
}

// ---------------- host-side dispatch ----------------------------------------
static bf16 *pAh, *pAl, *pBh, *pBl, *pSAh, *pSAl;

static void pg(int M, int N, int K, const bf16* Ah, const bf16* Al,
               const float* Cin, float* C, float alpha, float beta)
{
    if (N == BB) {
        dim3 grd(N / 128, M / 128);
        pgemm<128><<<grd, 256>>>(M, N, K, Ah, Al, pBh, pBl, Cin, C, alpha, beta);
    } else {
        dim3 grd(N / 64, M / 64);
        pgemm<64><<<grd, 128>>>(M, N, K, Ah, Al, pBh, pBl, Cin, C, alpha, beta);
    }
}
static void splitA(const float* src, int n) {
    split_kernel<<<(n / 4 + 255) / 256, 256>>>((const float4*)src, pAh, pAl, n / 4);
}
static void splitBplain(const float* src, int n) {  // B plane = src as-is (B = src^T)
    split_kernel<<<(n / 4 + 255) / 256, 256>>>((const float4*)src, pBh, pBl, n / 4);
}
static void splitBT(const float* src, int R, int C) {  // B plane = src^T ([C,R])
    splitT_kernel<<<dim3(C / 32, R / 32), dim3(32, 8)>>>(src, pBh, pBl, R, C);
}
static void splitBoth(const float* src, int R, int C) {
    split_both_kernel<<<dim3(C / 32, R / 32), dim3(32, 8)>>>(src, pAh, pAl, pBh, pBl, R, C);
}

extern "C" void kernel_launch(void* const* d_in, const int* in_sizes, int n_in,
                              void* d_out, int out_size)
{
    (void)in_sizes; (void)n_in; (void)out_size;
    const float* state     = (const float*)d_in[0];
    const float* state_cov = (const float*)d_in[1];
    const float* meas      = (const float*)d_in[2];
    const float* control   = (const float*)d_in[3];
    const float* F         = (const float*)d_in[4];
    const float* Q         = (const float*)d_in[5];
    const float* Bc        = (const float*)d_in[6];
    const float* H         = (const float*)d_in[7];
    const float* R         = (const float*)d_in[8];
    float* out_state = (float*)d_out;
    float* out_cov   = out_state + (size_t)DD * BB;

    float *sp, *fs, *cp, *innov, *hp, *S, *X, *X2, *T, *pht, *Kg, *norms;
    cudaGetSymbolAddress((void**)&sp,    g_state_p);
    cudaGetSymbolAddress((void**)&fs,    g_FS);
    cudaGetSymbolAddress((void**)&cp,    g_cov_p);
    cudaGetSymbolAddress((void**)&innov, g_innov);
    cudaGetSymbolAddress((void**)&hp,    g_HP);
    cudaGetSymbolAddress((void**)&S,     g_S);
    cudaGetSymbolAddress((void**)&X,     g_X);
    cudaGetSymbolAddress((void**)&X2,    g_X2);
    cudaGetSymbolAddress((void**)&T,     g_T);
    cudaGetSymbolAddress((void**)&pht,   g_PHt);
    cudaGetSymbolAddress((void**)&Kg,    g_K);
    cudaGetSymbolAddress((void**)&norms, g_norms);
    cudaGetSymbolAddress((void**)&pAh,   g_Ah);
    cudaGetSymbolAddress((void**)&pAl,   g_Al);
    cudaGetSymbolAddress((void**)&pBh,   g_Bh);
    cudaGetSymbolAddress((void**)&pBl,   g_Bl);
    cudaGetSymbolAddress((void**)&pSAh,  g_SAh);
    cudaGetSymbolAddress((void**)&pSAl,  g_SAl);

    // ---- prediction ----
    splitA(F, DD * DD);
    splitBT(state, DD, BB);
    pg(DD, BB, DD, pAh, pAl, nullptr, sp, 1.f, 0.f);       // sp = F @ state
    splitBT(state_cov, DD, DD);
    pg(DD, DD, DD, pAh, pAl, nullptr, fs, 1.f, 0.f);       // fs = F @ Sigma
    splitA(fs, DD * DD);
    splitBplain(F, DD * DD);                               // B = F^T
    pg(DD, DD, DD, pAh, pAl, Q, cp, 1.f, 1.f);             // cp = fs @ F^T + Q
    splitA(Bc, DD * CC);
    splitBT(control, CC, BB);
    pg(DD, BB, CC, pAh, pAl, sp, sp, 1.f, 1.f);            // sp += Bc @ control

    // ---- correction ----
    splitA(H, MM * DD);
    splitBT(sp, DD, BB);
    pg(MM, BB, DD, pAh, pAl, meas, innov, -1.f, 1.f);      // innov = meas - H@sp
    splitBT(cp, DD, DD);
    pg(MM, DD, DD, pAh, pAl, nullptr, hp, 1.f, 0.f);       // hp = H @ cp
    splitA(hp, MM * DD);
    splitBplain(H, MM * DD);                               // B = H^T
    pg(MM, MM, DD, pAh, pAl, R, S, 1.f, 1.f);              // S = hp @ H^T + R
    splitA(cp, DD * DD);
    pg(DD, MM, DD, pAh, pAl, nullptr, pht, 1.f, 0.f);      // pht = cp @ H^T

    // ---- Newton-Schulz inverse of S (tensor cores) ----
    zero_norms_kernel<<<1, 32>>>(norms);
    snorms_kernel<<<MM, 256>>>(S, norms);
    init_X_kernel<<<(MM * MM) / 256, 256>>>(S, norms, X);
    // S A-planes (fixed across iterations)
    split_kernel<<<(MM * MM / 4 + 255) / 256, 256>>>((const float4*)S, pSAh, pSAl,
                                                     MM * MM / 4);
    float* cur = X;
    float* nxt = X2;
    for (int it = 0; it < NS_ITERS; ++it) {
        splitBoth(cur, MM, MM);                            // A=cur, B=cur^T
        pg(MM, MM, MM, pSAh, pSAl, nullptr, T, 1.f, 0.f);  // T = S @ cur
        splitBT(T, MM, MM);                                // B = T^T
        pg(MM, MM, MM, pAh, pAl, cur, nxt, -1.f, 2.f);     // X' = 2X - X@T
        float* tmpp = cur; cur = nxt; nxt = tmpp;
    }
    // cur == S^{-1}

    // ---- gain + outputs ----
    splitA(pht, DD * MM);
    splitBT(cur, MM, MM);
    pg(DD, MM, MM, pAh, pAl, nullptr, Kg, 1.f, 0.f);       // Kg = pht @ S^{-1}
    splitA(Kg, DD * MM);
    splitBT(innov, MM, BB);
    pg(DD, BB, MM, pAh, pAl, sp, out_state, 1.f, 1.f);     // state_n
    splitBT(hp, MM, DD);
    pg(DD, DD, MM, pAh, pAl, cp, out_cov, -1.f, 1.f);      // cov_n = cp - Kg@hp
}